// round 14
// baseline (speedup 1.0000x reference)
#include <cuda_runtime.h>
#include <cuda_fp16.h>
#include <cstdint>
#include <math.h>

#define Bv 4
#define Lv 2048
#define Kv 32
#define CD 128
#define NCH 7
#define NKSG 28
#define GRIDF (Bv*Lv/4)   // 2048 fused CTAs, 4 residues each

// Scratch
__device__ float g_atoms[Bv*Lv*5*3];
__device__ float g_ca[Bv*Lv*3];
__device__ uint2 g_Wf[NKSG*16*32];   // W fragments [ksg][nt][lane]

__constant__ int c_PA[24] = {0,2,3,4,1,1,1,1,0,0,0,4,4,3,0,2,3,4,2,3,4,2,3,2};
__constant__ int c_PB[24] = {0,2,3,4,0,2,3,4,2,3,4,2,3,2,1,1,1,1,0,0,0,4,4,3};

__device__ __forceinline__ unsigned smem_u32(const void* p) {
    unsigned a;
    asm("{ .reg .u64 t; cvta.to.shared.u64 t, %1; cvt.u32.u64 %0, t; }" : "=r"(a) : "l"(p));
    return a;
}
__device__ __forceinline__ void ldsm4(unsigned* r, unsigned addr) {
    asm volatile("ldmatrix.sync.aligned.m8n8.x4.shared.b16 {%0,%1,%2,%3}, [%4];"
        : "=r"(r[0]), "=r"(r[1]), "=r"(r[2]), "=r"(r[3]) : "r"(addr));
}
__device__ __forceinline__ void mma16816(float* c, const unsigned* a, unsigned b0, unsigned b1) {
    asm volatile("mma.sync.aligned.m16n8k16.row.col.f32.f16.f16.f32 "
        "{%0,%1,%2,%3},{%4,%5,%6,%7},{%8,%9},{%0,%1,%2,%3};"
        : "+f"(c[0]), "+f"(c[1]), "+f"(c[2]), "+f"(c[3])
        : "r"(a[0]), "r"(a[1]), "r"(a[2]), "r"(a[3]), "r"(b0), "r"(b1));
}
__device__ __forceinline__ unsigned long long umin64(unsigned long long a, unsigned long long b) {
    return a < b ? a : b;
}

// ---------------------------------------------------------------------------
// k0: W_edge -> single fp16 fragments in mma b-frag layout.
// ---------------------------------------------------------------------------
__global__ void k0_prepW(const float* __restrict__ W) {
    int idx = blockIdx.x * 256 + threadIdx.x;
    if (idx >= NKSG*16*32) return;
    int lane = idx & 31;
    int nt   = (idx >> 5) & 15;
    int ksg  = idx >> 9;
    int n  = nt*8 + (lane >> 2);
    int k0 = ksg*16 + (lane & 3)*2;
    unsigned r[2];
    #pragma unroll
    for (int h = 0; h < 2; h++) {
        int f0 = k0 + h*8;
        float v0 = (f0   < 416) ? W[f0 * CD + n]     : 0.0f;
        float v1 = (f0+1 < 416) ? W[(f0+1) * CD + n] : 0.0f;
        __half2 p = __floats2half2_rn(v0, v1);
        r[h] = *(unsigned*)&p;
    }
    g_Wf[idx] = make_uint2(r[0], r[1]);
}

// ---------------------------------------------------------------------------
// k1: atom table (N, Ca, C, O, Cb)
// ---------------------------------------------------------------------------
__global__ void k1_atoms(const float* __restrict__ X) {
    int i = blockIdx.x * blockDim.x + threadIdx.x;
    if (i >= Bv*Lv) return;
    const float* x = X + (size_t)i * 12;
    float Nx=x[0],Ny=x[1],Nz=x[2];
    float Ax=x[3],Ay=x[4],Az=x[5];
    float Cx=x[6],Cy=x[7],Cz=x[8];
    float Ox=x[9],Oy=x[10],Oz=x[11];
    float bx=Ax-Nx, by=Ay-Ny, bz=Az-Nz;
    float cx=Cx-Ax, cy=Cy-Ay, cz=Cz-Az;
    float ax=by*cz-bz*cy, ay=bz*cx-bx*cz, az=bx*cy-by*cx;
    float Cbx = -0.58273431f*ax + 0.56802827f*bx - 0.54067466f*cx + Ax;
    float Cby = -0.58273431f*ay + 0.56802827f*by - 0.54067466f*cy + Ay;
    float Cbz = -0.58273431f*az + 0.56802827f*bz - 0.54067466f*cz + Az;
    float* p = g_atoms + (size_t)i * 15;
    p[0]=Nx; p[1]=Ny; p[2]=Nz;
    p[3]=Ax; p[4]=Ay; p[5]=Az;
    p[6]=Cx; p[7]=Cy; p[8]=Cz;
    p[9]=Ox; p[10]=Oy; p[11]=Oz;
    p[12]=Cbx; p[13]=Cby; p[14]=Cbz;
    g_ca[i*3+0]=Ax; g_ca[i*3+1]=Ay; g_ca[i*3+2]=Az;
}

// ---------------------------------------------------------------------------
// kF: FUSED top-K + feature-build + fp16 mma GEMM + LayerNorm.
// Phase 1 (= proven k2): distances + 32 selection rounds -> jv/Dn in smem.
// Phase 2 (= proven R13 k3): double-buffered A build + 2x4 warp-tile MMA.
// Smem phase-overlaid: A-buffers/nbA alias the dead ca/dist regions.
// ---------------------------------------------------------------------------
// phase 1 regions
#define F_CA   0                          // 2048*3*4 = 24576
#define F_DS   24576                      // 4*2048*4 = 32768 -> 57344
#define F_TMIN 57344                      // 4*256*8  = 8192  -> 65536
// phase 2 regions (alias dead phase-1 space)
#define F_A0   0                          // 18432
#define F_A1   18432                      // -> 36864
#define F_NBA  36864                      // 7680 -> 44544
// persistent metadata (above both)
#define F_QA   65536                      // 240
#define F_JV   65792                      // 512
#define F_DN   66304                      // 512
#define F_DP   66816                      // 512
#define F_S1   67328                      // 512
#define F_S2   67840                      // 512
#define F_TOT  68352

__global__ void __launch_bounds__(256, 2)
kF_fused(const float* __restrict__ mask,
         const int* __restrict__ ridx, const int* __restrict__ chl,
         const float* __restrict__ Wpos, const float* __restrict__ bpos,
         const float* __restrict__ gamma, const float* __restrict__ beta,
         float* __restrict__ out, int write_idx) {
    extern __shared__ unsigned char sm[];
    unsigned sb = smem_u32(sm);
    __shared__ int s_maxi[4];

    int tid  = threadIdx.x;
    int wid  = tid >> 5, lane = tid & 31;
    int row0 = blockIdx.x * 4;
    int b    = row0 >> 11;

    float* ca_s = (float*)(sm + F_CA);
    float* d_s  = (float*)(sm + F_DS);
    unsigned long long* tmin = (unsigned long long*)(sm + F_TMIN);
    float* qa   = (float*)(sm + F_QA);
    int*   jv   = (int*)  (sm + F_JV);
    float* Dn   = (float*)(sm + F_DN);
    int*   dpos = (int*)  (sm + F_DP);
    float* s_s1 = (float*)(sm + F_S1);
    float* s_s2 = (float*)(sm + F_S2);

    // ---------------- phase 1: top-K (proven k2 structure) ----------------
    if (tid < 4) s_maxi[tid] = 0;
    if (tid < 128) { s_s1[tid] = 0.0f; s_s2[tid] = 0.0f; }
    if (tid >= 160 && tid < 220) {
        int t = tid - 160;
        qa[t] = g_atoms[(size_t)(row0 + t/15)*15 + (t%15)];
    }
    const float* cab = g_ca + (size_t)b * Lv * 3;
    for (int i = tid; i < Lv*3; i += 256) ca_s[i] = cab[i];
    __syncthreads();

    {
        float cx[4], cy[4], cz[4], mi[4];
        #pragma unroll
        for (int r = 0; r < 4; r++) {
            int li = (row0 + r) & (Lv-1);
            cx[r] = ca_s[li*3+0]; cy[r] = ca_s[li*3+1]; cz[r] = ca_s[li*3+2];
            mi[r] = mask[(size_t)row0 + r];
        }
        const float* mb = mask + (size_t)b * Lv;

        int j0 = tid * 8;
        float Dreg[4][8], mbj[8];
        float lmax[4] = {0.f, 0.f, 0.f, 0.f};
        #pragma unroll
        for (int s = 0; s < 8; s++) {
            int j = j0 + s;
            float px = ca_s[j*3+0], py = ca_s[j*3+1], pz = ca_s[j*3+2];
            mbj[s] = mb[j];
            #pragma unroll
            for (int r = 0; r < 4; r++) {
                float dx = cx[r]-px, dy = cy[r]-py, dz = cz[r]-pz;
                float d  = sqrtf(dx*dx + dy*dy + dz*dz + 1e-6f);
                float D  = mi[r] * mbj[s] * d;
                Dreg[r][s] = D;
                lmax[r] = fmaxf(lmax[r], D);
            }
        }
        #pragma unroll
        for (int r = 0; r < 4; r++) {
            float v = lmax[r];
            #pragma unroll
            for (int o = 16; o; o >>= 1) v = fmaxf(v, __shfl_xor_sync(0xffffffffu, v, o));
            if (lane == 0) atomicMax(&s_maxi[r], __float_as_int(v));
        }
        __syncthreads();

        #pragma unroll
        for (int r = 0; r < 4; r++) {
            float Dmax = __int_as_float(s_maxi[r]);
            unsigned long long mn = ~0ULL;
            #pragma unroll
            for (int s = 0; s < 8; s++) {
                int j = j0 + s;
                float m2 = mi[r] * mbj[s];
                float Dadj = Dreg[r][s] + (1.0f - m2) * Dmax;
                d_s[r*Lv + j] = Dadj;
                unsigned long long k = (((unsigned long long)__float_as_uint(Dadj)) << 32) | (unsigned)j;
                mn = umin64(mn, k);
            }
            tmin[r*256 + tid] = mn;
        }
    }
    __syncthreads();

    // selection: warps 0-3, one row each; results -> smem jv/Dn
    if (wid < 4) {
        int r = wid;
        float* dr = d_s + r*Lv;
        unsigned long long m[8];
        #pragma unroll
        for (int s = 0; s < 8; s++) m[s] = tmin[r*256 + lane*8 + s];

        for (int rnd = 0; rnd < Kv; rnd++) {
            unsigned long long w = m[0];
            #pragma unroll
            for (int s = 1; s < 8; s++) w = umin64(w, m[s]);
            #pragma unroll
            for (int o = 16; o; o >>= 1) {
                unsigned long long v = __shfl_xor_sync(0xffffffffu, w, o);
                w = umin64(w, v);
            }
            int j = (int)(unsigned)(w & 0xffffffffu);
            if (lane == 0) {
                jv[r*Kv + rnd] = j;
                Dn[r*Kv + rnd] = __uint_as_float((unsigned)(w >> 32));
            }
            int t = j >> 3;
            if ((t >> 3) == lane) {
                dr[j] = __int_as_float(0x7f800000);
                unsigned long long nm = ~0ULL;
                #pragma unroll
                for (int s = 0; s < 8; s++) {
                    int jj = t*8 + s;
                    float Dv = dr[jj];
                    unsigned long long k = (((unsigned long long)__float_as_uint(Dv)) << 32) | (unsigned)jj;
                    nm = umin64(nm, k);
                }
                m[t & 7] = nm;
            }
        }
    }
    __syncthreads();   // jv/Dn ready; d_s/ca_s/tmin now DEAD

    // ---------------- phase 2: features + GEMM (proven R13 structure) ------
    int e  = tid & 127;
    int s0 = tid >> 7;
    int r  = e >> 5;
    int wr = wid >> 2;
    int wc = wid & 3;

    // per-edge scalars + E_idx write + neighbor gather
    if (tid < 128) {
        int brow = row0 + r;
        int j = jv[tid];
        int off = ridx[brow] - ridx[(size_t)b*Lv + j];
        int ech = (chl[brow] == chl[(size_t)b*Lv + j]) ? 1 : 0;
        int d = off + 32;
        d = d < 0 ? 0 : (d > 64 ? 64 : d);
        dpos[tid] = ech ? d : 65;
        if (write_idx)
            out[(size_t)Bv*Lv*Kv*CD + (size_t)row0*Kv + tid] = (float)j;
    }
    float* nbA = (float*)(sm + F_NBA);
    for (int t = tid; t < 128*15; t += 256) {
        nbA[t] = g_atoms[((size_t)b*Lv + jv[t/15])*15 + (t%15)];
    }
    __syncthreads();

    auto build_chunk = [&](int kcb, unsigned abuf) {
        #pragma unroll
        for (int pp = 0; pp < 2; pp++) {
            int ss = s0 + pp*2;
            int S  = kcb*4 + ss;
            if (S < 26) {
                float vals[16];
                if (S == 0) {
                    const float4* wp = (const float4*)(Wpos + dpos[e]*16);
                    const float4* bb = (const float4*)bpos;
                    #pragma unroll
                    for (int q = 0; q < 4; q++) {
                        float4 a = wp[q], c = bb[q];
                        vals[q*4+0]=a.x+c.x; vals[q*4+1]=a.y+c.y; vals[q*4+2]=a.z+c.z; vals[q*4+3]=a.w+c.w;
                    }
                } else {
                    float D;
                    if (S == 1) D = Dn[e];
                    else {
                        int p = S - 2;
                        const float* A  = qa  + r*15 + c_PA[p]*3;
                        const float* Bp = nbA + e*15 + c_PB[p]*3;
                        float dx=A[0]-Bp[0], dy=A[1]-Bp[1], dz=A[2]-Bp[2];
                        D = sqrtf(dx*dx + dy*dy + dz*dz + 1e-6f);
                    }
                    #pragma unroll
                    for (int m = 0; m < 16; m++) {
                        float mu = 2.0f + (float)m * (4.0f/3.0f);
                        float z = (D - mu) * 0.8f;
                        vals[m] = __expf(-(z*z));
                    }
                }
                unsigned byteoff = abuf + (unsigned)e*144 + (unsigned)ss*32;
                #pragma unroll
                for (int q = 0; q < 2; q++) {
                    unsigned hp[4];
                    #pragma unroll
                    for (int j4 = 0; j4 < 4; j4++) {
                        __half2 h2 = __floats2half2_rn(vals[q*8 + j4*2], vals[q*8 + j4*2 + 1]);
                        hp[j4] = *(unsigned*)&h2;
                    }
                    *(uint4*)(sm + byteoff + q*16) = make_uint4(hp[0],hp[1],hp[2],hp[3]);
                }
            }
        }
    };

    float acc[4][4][4];
    #pragma unroll
    for (int mt = 0; mt < 4; mt++)
        #pragma unroll
        for (int nt = 0; nt < 4; nt++) {
            acc[mt][nt][0]=0.f; acc[mt][nt][1]=0.f; acc[mt][nt][2]=0.f; acc[mt][nt][3]=0.f;
        }

    int arow  = lane & 15;
    int acol8 = (lane >> 4) * 8;
    const uint2* __restrict__ Wf = g_Wf;

    build_chunk(0, F_A0);
    __syncthreads();

    for (int kc = 0; kc < NCH; kc++) {
        unsigned cur = (kc & 1) ? F_A1 : F_A0;
        unsigned nxt = (kc & 1) ? F_A0 : F_A1;
        unsigned aBase = sb + cur + (unsigned)(wr*64)*144;

        int nks = (kc == NCH-1) ? 2 : 4;
        for (int ks = 0; ks < nks; ks++) {
            int ksg = kc*4 + ks;
            int k0  = ks * 16;
            uint2 bf[4];
            #pragma unroll
            for (int nt = 0; nt < 4; nt++)
                bf[nt] = Wf[((ksg*16) + (wc*4 + nt))*32 + lane];
            unsigned a[4][4];
            #pragma unroll
            for (int mt = 0; mt < 4; mt++)
                ldsm4(a[mt], aBase + (unsigned)(mt*16 + arow)*144 + (unsigned)(k0 + acol8)*2);
            #pragma unroll
            for (int mt = 0; mt < 4; mt++)
                #pragma unroll
                for (int nt = 0; nt < 4; nt++)
                    mma16816(acc[mt][nt], a[mt], bf[nt].x, bf[nt].y);
        }

        if (kc + 1 < NCH) build_chunk(kc + 1, nxt);
        __syncthreads();
    }

    // LayerNorm partials
    #pragma unroll
    for (int mt = 0; mt < 4; mt++) {
        float pA1=0.f, pA2=0.f, pB1=0.f, pB2=0.f;
        #pragma unroll
        for (int nt = 0; nt < 4; nt++) {
            float v0 = acc[mt][nt][0], v1 = acc[mt][nt][1];
            float v2 = acc[mt][nt][2], v3 = acc[mt][nt][3];
            pA1 += v0 + v1;  pA2 += v0*v0 + v1*v1;
            pB1 += v2 + v3;  pB2 += v2*v2 + v3*v3;
        }
        #pragma unroll
        for (int o = 1; o <= 2; o <<= 1) {
            pA1 += __shfl_xor_sync(0xffffffffu, pA1, o);
            pA2 += __shfl_xor_sync(0xffffffffu, pA2, o);
            pB1 += __shfl_xor_sync(0xffffffffu, pB1, o);
            pB2 += __shfl_xor_sync(0xffffffffu, pB2, o);
        }
        if ((lane & 3) == 0) {
            int rA = wr*64 + mt*16 + (lane >> 2);
            atomicAdd(&s_s1[rA],     pA1);
            atomicAdd(&s_s2[rA],     pA2);
            atomicAdd(&s_s1[rA + 8], pB1);
            atomicAdd(&s_s2[rA + 8], pB2);
        }
    }
    __syncthreads();

    // normalize + write
    {
        int cb = wc*32 + 2*(lane & 3);
        float gv[4][2], bv[4][2];
        #pragma unroll
        for (int nt = 0; nt < 4; nt++) {
            gv[nt][0] = gamma[cb + nt*8];  gv[nt][1] = gamma[cb + nt*8 + 1];
            bv[nt][0] = beta[cb + nt*8];   bv[nt][1] = beta[cb + nt*8 + 1];
        }
        #pragma unroll
        for (int mt = 0; mt < 4; mt++) {
            int rA = wr*64 + mt*16 + (lane >> 2);
            int rB = rA + 8;
            float muA = s_s1[rA] * (1.0f/128.0f);
            float vrA = s_s2[rA] * (1.0f/128.0f) - muA*muA;
            float ivA = 1.0f / sqrtf(vrA + 1e-5f);
            float muB = s_s1[rB] * (1.0f/128.0f);
            float vrB = s_s2[rB] * (1.0f/128.0f) - muB*muB;
            float ivB = 1.0f / sqrtf(vrB + 1e-5f);
            float* opA = out + ((size_t)row0*Kv + rA) * CD;
            float* opB = out + ((size_t)row0*Kv + rB) * CD;
            #pragma unroll
            for (int nt = 0; nt < 4; nt++) {
                int c = cb + nt*8;
                float2 oA, oB;
                oA.x = (acc[mt][nt][0] - muA)*ivA*gv[nt][0] + bv[nt][0];
                oA.y = (acc[mt][nt][1] - muA)*ivA*gv[nt][1] + bv[nt][1];
                oB.x = (acc[mt][nt][2] - muB)*ivB*gv[nt][0] + bv[nt][0];
                oB.y = (acc[mt][nt][3] - muB)*ivB*gv[nt][1] + bv[nt][1];
                *(float2*)(opA + c) = oA;
                *(float2*)(opB + c) = oB;
            }
        }
    }
}

// ---------------------------------------------------------------------------
// Launch
// ---------------------------------------------------------------------------
extern "C" void kernel_launch(void* const* d_in, const int* in_sizes, int n_in,
                              void* d_out, int out_size) {
    const float* X     = (const float*)d_in[0];
    const float* mask  = (const float*)d_in[1];
    const int*   ridx  = (const int*)  d_in[2];
    const int*   chl   = (const int*)  d_in[3];
    const float* Wpos  = (const float*)d_in[4];
    const float* bpos  = (const float*)d_in[5];
    const float* Wedge = (const float*)d_in[6];
    const float* gamma = (const float*)d_in[7];
    const float* beta  = (const float*)d_in[8];
    float* out = (float*)d_out;

    cudaFuncSetAttribute(kF_fused, cudaFuncAttributeMaxDynamicSharedMemorySize, F_TOT);

    k0_prepW<<<(NKSG*16*32 + 255)/256, 256>>>(Wedge);
    k1_atoms<<<(Bv*Lv + 255)/256, 256>>>(X);

    long long e_elems = (long long)Bv*Lv*Kv*CD;
    int write_idx = ((long long)out_size >= e_elems + (long long)Bv*Lv*Kv) ? 1 : 0;
    kF_fused<<<GRIDF, 256, F_TOT>>>(mask, ridx, chl, Wpos, bpos, gamma, beta, out, write_idx);
}

// round 15
// speedup vs baseline: 1.0737x; 1.0737x over previous
#include <cuda_runtime.h>
#include <cuda_fp16.h>
#include <cstdint>
#include <math.h>

#define Bv 4
#define Lv 2048
#define Kv 32
#define CD 128
#define NCH 7           // K chunks of 64
#define NKSG 28         // total k-steps of 16 (26 real)
#define GRID3 (Bv*Lv/2) // 4096 CTAs, 2 residues (64 edges) each

// Scratch (__device__ globals; no allocation allowed)
__device__ float g_atoms[Bv*Lv*5*3];
__device__ float g_ca[Bv*Lv*3];
__device__ int   g_eidx[Bv*Lv*Kv];
__device__ float g_dn[Bv*Lv*Kv];
// W in mma b-fragment layout: [ksg(28)][nt(16)][lane(32)] -> uint2 {b0,b1}, single fp16
__device__ uint2 g_Wf[NKSG*16*32];

__constant__ int c_PA[24] = {0,2,3,4,1,1,1,1,0,0,0,4,4,3,0,2,3,4,2,3,4,2,3,2};
__constant__ int c_PB[24] = {0,2,3,4,0,2,3,4,2,3,4,2,3,2,1,1,1,1,0,0,0,4,4,3};

__device__ __forceinline__ unsigned smem_u32(const void* p) {
    unsigned a;
    asm("{ .reg .u64 t; cvta.to.shared.u64 t, %1; cvt.u32.u64 %0, t; }" : "=r"(a) : "l"(p));
    return a;
}
__device__ __forceinline__ void ldsm4(unsigned* r, unsigned addr) {
    asm volatile("ldmatrix.sync.aligned.m8n8.x4.shared.b16 {%0,%1,%2,%3}, [%4];"
        : "=r"(r[0]), "=r"(r[1]), "=r"(r[2]), "=r"(r[3]) : "r"(addr));
}
__device__ __forceinline__ void mma16816(float* c, const unsigned* a, unsigned b0, unsigned b1) {
    asm volatile("mma.sync.aligned.m16n8k16.row.col.f32.f16.f16.f32 "
        "{%0,%1,%2,%3},{%4,%5,%6,%7},{%8,%9},{%0,%1,%2,%3};"
        : "+f"(c[0]), "+f"(c[1]), "+f"(c[2]), "+f"(c[3])
        : "r"(a[0]), "r"(a[1]), "r"(a[2]), "r"(a[3]), "r"(b0), "r"(b1));
}
__device__ __forceinline__ unsigned long long umin64(unsigned long long a, unsigned long long b) {
    return a < b ? a : b;
}

// ---------------------------------------------------------------------------
// k0: W_edge (416x128 f32) -> single fp16 fragments in mma b-frag layout.
// ---------------------------------------------------------------------------
__global__ void k0_prepW(const float* __restrict__ W) {
    int idx = blockIdx.x * 256 + threadIdx.x;     // NKSG*16*32 = 14336
    if (idx >= NKSG*16*32) return;
    int lane = idx & 31;
    int nt   = (idx >> 5) & 15;
    int ksg  = idx >> 9;
    int n  = nt*8 + (lane >> 2);
    int k0 = ksg*16 + (lane & 3)*2;
    unsigned r[2];
    #pragma unroll
    for (int h = 0; h < 2; h++) {
        int f0 = k0 + h*8;
        float v0 = (f0   < 416) ? W[f0 * CD + n]     : 0.0f;
        float v1 = (f0+1 < 416) ? W[(f0+1) * CD + n] : 0.0f;
        __half2 p = __floats2half2_rn(v0, v1);
        r[h] = *(unsigned*)&p;
    }
    g_Wf[idx] = make_uint2(r[0], r[1]);
}

// ---------------------------------------------------------------------------
// k1: atom table (N, Ca, C, O, Cb)
// ---------------------------------------------------------------------------
__global__ void k1_atoms(const float* __restrict__ X) {
    int i = blockIdx.x * blockDim.x + threadIdx.x;
    if (i >= Bv*Lv) return;
    const float* x = X + (size_t)i * 12;
    float Nx=x[0],Ny=x[1],Nz=x[2];
    float Ax=x[3],Ay=x[4],Az=x[5];
    float Cx=x[6],Cy=x[7],Cz=x[8];
    float Ox=x[9],Oy=x[10],Oz=x[11];
    float bx=Ax-Nx, by=Ay-Ny, bz=Az-Nz;
    float cx=Cx-Ax, cy=Cy-Ay, cz=Cz-Az;
    float ax=by*cz-bz*cy, ay=bz*cx-bx*cz, az=bx*cy-by*cx;
    float Cbx = -0.58273431f*ax + 0.56802827f*bx - 0.54067466f*cx + Ax;
    float Cby = -0.58273431f*ay + 0.56802827f*by - 0.54067466f*cy + Ay;
    float Cbz = -0.58273431f*az + 0.56802827f*bz - 0.54067466f*cz + Az;
    float* p = g_atoms + (size_t)i * 15;
    p[0]=Nx; p[1]=Ny; p[2]=Nz;
    p[3]=Ax; p[4]=Ay; p[5]=Az;
    p[6]=Cx; p[7]=Cy; p[8]=Cz;
    p[9]=Ox; p[10]=Oy; p[11]=Oz;
    p[12]=Cbx; p[13]=Cby; p[14]=Cbz;
    g_ca[i*3+0]=Ax; g_ca[i*3+1]=Ay; g_ca[i*3+2]=Az;
}

// ---------------------------------------------------------------------------
// k2: top-K, 4 rows per 256-thread CTA (proven R10/R13 version).
// ---------------------------------------------------------------------------
__global__ void __launch_bounds__(256)
k2_topk(const float* __restrict__ mask) {
    extern __shared__ char smem_raw[];
    float* ca_s = (float*)smem_raw;
    float* d_s  = ca_s + Lv*3;
    unsigned long long* tmin = (unsigned long long*)(d_s + 4*Lv);
    __shared__ int s_maxi[4];

    int tid  = threadIdx.x;
    int wid  = tid >> 5, lane = tid & 31;
    int row0 = blockIdx.x * 4;
    int b    = row0 >> 11;

    if (tid < 4) s_maxi[tid] = 0;
    const float* cab = g_ca + (size_t)b * Lv * 3;
    for (int i = tid; i < Lv*3; i += 256) ca_s[i] = cab[i];
    __syncthreads();

    float cx[4], cy[4], cz[4], mi[4];
    #pragma unroll
    for (int r = 0; r < 4; r++) {
        int li = (row0 + r) & (Lv-1);
        cx[r] = ca_s[li*3+0]; cy[r] = ca_s[li*3+1]; cz[r] = ca_s[li*3+2];
        mi[r] = mask[(size_t)row0 + r];
    }
    const float* mb = mask + (size_t)b * Lv;

    int j0 = tid * 8;
    float Dreg[4][8], mbj[8];
    float lmax[4] = {0.f, 0.f, 0.f, 0.f};
    #pragma unroll
    for (int s = 0; s < 8; s++) {
        int j = j0 + s;
        float px = ca_s[j*3+0], py = ca_s[j*3+1], pz = ca_s[j*3+2];
        mbj[s] = mb[j];
        #pragma unroll
        for (int r = 0; r < 4; r++) {
            float dx = cx[r]-px, dy = cy[r]-py, dz = cz[r]-pz;
            float d  = sqrtf(dx*dx + dy*dy + dz*dz + 1e-6f);
            float D  = mi[r] * mbj[s] * d;
            Dreg[r][s] = D;
            lmax[r] = fmaxf(lmax[r], D);
        }
    }
    #pragma unroll
    for (int r = 0; r < 4; r++) {
        float v = lmax[r];
        #pragma unroll
        for (int o = 16; o; o >>= 1) v = fmaxf(v, __shfl_xor_sync(0xffffffffu, v, o));
        if (lane == 0) atomicMax(&s_maxi[r], __float_as_int(v));
    }
    __syncthreads();

    #pragma unroll
    for (int r = 0; r < 4; r++) {
        float Dmax = __int_as_float(s_maxi[r]);
        unsigned long long mn = ~0ULL;
        #pragma unroll
        for (int s = 0; s < 8; s++) {
            int j = j0 + s;
            float m2 = mi[r] * mbj[s];
            float Dadj = Dreg[r][s] + (1.0f - m2) * Dmax;
            d_s[r*Lv + j] = Dadj;
            unsigned long long k = (((unsigned long long)__float_as_uint(Dadj)) << 32) | (unsigned)j;
            mn = umin64(mn, k);
        }
        tmin[r*256 + tid] = mn;
    }
    __syncthreads();

    if (wid < 4) {
        int r = wid;
        int row = row0 + r;
        float* dr = d_s + r*Lv;
        unsigned long long m[8];
        #pragma unroll
        for (int s = 0; s < 8; s++) m[s] = tmin[r*256 + lane*8 + s];

        for (int rnd = 0; rnd < Kv; rnd++) {
            unsigned long long w = m[0];
            #pragma unroll
            for (int s = 1; s < 8; s++) w = umin64(w, m[s]);
            #pragma unroll
            for (int o = 16; o; o >>= 1) {
                unsigned long long v = __shfl_xor_sync(0xffffffffu, w, o);
                w = umin64(w, v);
            }
            int j = (int)(unsigned)(w & 0xffffffffu);
            if (lane == 0) {
                g_eidx[(size_t)row*Kv + rnd] = j;
                g_dn[(size_t)row*Kv + rnd]   = __uint_as_float((unsigned)(w >> 32));
            }
            int t = j >> 3;
            if ((t >> 3) == lane) {
                dr[j] = __int_as_float(0x7f800000);
                unsigned long long nm = ~0ULL;
                #pragma unroll
                for (int s = 0; s < 8; s++) {
                    int jj = t*8 + s;
                    float Dv = dr[jj];
                    unsigned long long k = (((unsigned long long)__float_as_uint(Dv)) << 32) | (unsigned)jj;
                    nm = umin64(nm, k);
                }
                m[t & 7] = nm;
            }
        }
    }
}

// ---------------------------------------------------------------------------
// k3: fused feature-build + single-pass fp16 mma GEMM + LayerNorm.
// CTA = 2 residues (64 edges, M=64). Warp grid 2(M) x 4(N): warp tile
// 32 rows x 32 cols -> acc = 32 regs, targeting 3 CTAs/SM (occ +50%).
// A double-buffered (R13-proven pipelining); each thread builds exactly
// one 16-value sub-block per chunk.
// ---------------------------------------------------------------------------
#define S_A0  0                           // 64*144 = 9216
#define S_A1  9216                        // -> 18432
#define S_NBA 18432                       // 64*15 f32 = 3840 -> 22272
#define S_QA  22272                       // 30 f32 -> 128 (padded)
#define S_JV  22400                       // 64 int -> 256
#define S_DN  22656                       // 64 f32 -> 256
#define S_DP  22912                       // 64 int -> 256
#define S_S1  23168                       // 64 f32 -> 256
#define S_S2  23424                       // 64 f32 -> 256
#define S_TOT 23680

__global__ void __launch_bounds__(256, 3)
k3_mma(const int* __restrict__ ridx, const int* __restrict__ chl,
       const float* __restrict__ Wpos, const float* __restrict__ bpos,
       const float* __restrict__ gamma, const float* __restrict__ beta,
       float* __restrict__ out, int write_idx) {
    extern __shared__ unsigned char sm[];
    unsigned sb = smem_u32(sm);
    int tid  = threadIdx.x;
    int wid  = tid >> 5, lane = tid & 31;
    int wr   = wid >> 2;                 // M group: rows wr*32..wr*32+31
    int wc   = wid & 3;                  // N group: cols wc*32..wc*32+31
    int row0 = blockIdx.x * 2;           // 2 residues
    int b    = row0 >> 11;

    float* nbA  = (float*)(sm + S_NBA);
    float* qa   = (float*)(sm + S_QA);
    int*   jv   = (int*)  (sm + S_JV);
    float* Dn   = (float*)(sm + S_DN);
    int*   dpos = (int*)  (sm + S_DP);
    float* s_s1 = (float*)(sm + S_S1);
    float* s_s2 = (float*)(sm + S_S2);

    if (tid < 64) {
        int r = tid >> 5;
        int brow = row0 + r;
        int j = g_eidx[(size_t)row0*Kv + tid];
        jv[tid] = j;
        Dn[tid] = g_dn[(size_t)row0*Kv + tid];
        int off = ridx[brow] - ridx[(size_t)b*Lv + j];
        int ech = (chl[brow] == chl[(size_t)b*Lv + j]) ? 1 : 0;
        int d = off + 32;
        d = d < 0 ? 0 : (d > 64 ? 64 : d);
        dpos[tid] = ech ? d : 65;
        s_s1[tid] = 0.0f;
        s_s2[tid] = 0.0f;
    }
    if (tid >= 160 && tid < 190) {       // 2 residues x 15 query atoms
        int t = tid - 160;
        qa[t] = g_atoms[(size_t)(row0 + t/15)*15 + (t%15)];
    }
    __syncthreads();

    for (int t = tid; t < 64*15; t += 256) {
        nbA[t] = g_atoms[((size_t)b*Lv + jv[t/15])*15 + (t%15)];
    }
    __syncthreads();

    int e  = tid & 63;                   // edge 0..63
    int ss = tid >> 6;                   // sub-block 0..3 within chunk
    int r  = e >> 5;                     // residue 0..1

    // build: each thread fills ONE 16-value sub-block per chunk
    auto build_chunk = [&](int kcb, unsigned abuf) {
        int S = kcb*4 + ss;
        if (S < 26) {
            float vals[16];
            if (S == 0) {
                const float4* wp = (const float4*)(Wpos + dpos[e]*16);
                const float4* bb = (const float4*)bpos;
                #pragma unroll
                for (int q = 0; q < 4; q++) {
                    float4 a = wp[q], c = bb[q];
                    vals[q*4+0]=a.x+c.x; vals[q*4+1]=a.y+c.y; vals[q*4+2]=a.z+c.z; vals[q*4+3]=a.w+c.w;
                }
            } else {
                float D;
                if (S == 1) D = Dn[e];
                else {
                    int p = S - 2;
                    const float* A  = qa  + r*15 + c_PA[p]*3;
                    const float* Bp = nbA + e*15 + c_PB[p]*3;
                    float dx=A[0]-Bp[0], dy=A[1]-Bp[1], dz=A[2]-Bp[2];
                    D = sqrtf(dx*dx + dy*dy + dz*dz + 1e-6f);
                }
                #pragma unroll
                for (int m = 0; m < 16; m++) {
                    float mu = 2.0f + (float)m * (4.0f/3.0f);
                    float z = (D - mu) * 0.8f;
                    vals[m] = __expf(-(z*z));
                }
            }
            unsigned byteoff = abuf + (unsigned)e*144 + (unsigned)ss*32;
            #pragma unroll
            for (int q = 0; q < 2; q++) {
                unsigned hp[4];
                #pragma unroll
                for (int j4 = 0; j4 < 4; j4++) {
                    __half2 h2 = __floats2half2_rn(vals[q*8 + j4*2], vals[q*8 + j4*2 + 1]);
                    hp[j4] = *(unsigned*)&h2;
                }
                *(uint4*)(sm + byteoff + q*16) = make_uint4(hp[0],hp[1],hp[2],hp[3]);
            }
        }
    };

    // acc[mt][nt][4]: rows wr*32 + mt*16, cols wc*32 + nt*8
    float acc[2][4][4];
    #pragma unroll
    for (int mt = 0; mt < 2; mt++)
        #pragma unroll
        for (int nt = 0; nt < 4; nt++) {
            acc[mt][nt][0]=0.f; acc[mt][nt][1]=0.f; acc[mt][nt][2]=0.f; acc[mt][nt][3]=0.f;
        }

    int arow  = lane & 15;
    int acol8 = (lane >> 4) * 8;
    const uint2* __restrict__ Wf = g_Wf;

    build_chunk(0, S_A0);
    __syncthreads();

    for (int kc = 0; kc < NCH; kc++) {
        unsigned cur = (kc & 1) ? S_A1 : S_A0;
        unsigned nxt = (kc & 1) ? S_A0 : S_A1;
        unsigned aBase = sb + cur + (unsigned)(wr*32)*144;

        int nks = (kc == NCH-1) ? 2 : 4;
        for (int ks = 0; ks < nks; ks++) {
            int ksg = kc*4 + ks;
            int k0  = ks * 16;
            uint2 bf[4];
            #pragma unroll
            for (int nt = 0; nt < 4; nt++)
                bf[nt] = Wf[((ksg*16) + (wc*4 + nt))*32 + lane];
            unsigned a[2][4];
            #pragma unroll
            for (int mt = 0; mt < 2; mt++)
                ldsm4(a[mt], aBase + (unsigned)(mt*16 + arow)*144 + (unsigned)(k0 + acol8)*2);
            #pragma unroll
            for (int mt = 0; mt < 2; mt++)
                #pragma unroll
                for (int nt = 0; nt < 4; nt++)
                    mma16816(acc[mt][nt], a[mt], bf[nt].x, bf[nt].y);
        }

        if (kc + 1 < NCH) build_chunk(kc + 1, nxt);
        __syncthreads();
    }

    if (write_idx && tid < 64) {
        out[(size_t)Bv*Lv*Kv*CD + (size_t)row0*Kv + tid] = (float)jv[tid];
    }

    // LayerNorm partials: warp covers 32 cols for rows in its 32-row band
    #pragma unroll
    for (int mt = 0; mt < 2; mt++) {
        float pA1=0.f, pA2=0.f, pB1=0.f, pB2=0.f;
        #pragma unroll
        for (int nt = 0; nt < 4; nt++) {
            float v0 = acc[mt][nt][0], v1 = acc[mt][nt][1];
            float v2 = acc[mt][nt][2], v3 = acc[mt][nt][3];
            pA1 += v0 + v1;  pA2 += v0*v0 + v1*v1;
            pB1 += v2 + v3;  pB2 += v2*v2 + v3*v3;
        }
        #pragma unroll
        for (int o = 1; o <= 2; o <<= 1) {
            pA1 += __shfl_xor_sync(0xffffffffu, pA1, o);
            pA2 += __shfl_xor_sync(0xffffffffu, pA2, o);
            pB1 += __shfl_xor_sync(0xffffffffu, pB1, o);
            pB2 += __shfl_xor_sync(0xffffffffu, pB2, o);
        }
        if ((lane & 3) == 0) {
            int rA = wr*32 + mt*16 + (lane >> 2);
            atomicAdd(&s_s1[rA],     pA1);
            atomicAdd(&s_s2[rA],     pA2);
            atomicAdd(&s_s1[rA + 8], pB1);
            atomicAdd(&s_s2[rA + 8], pB2);
        }
    }
    __syncthreads();

    // normalize + write: warp writes its 32-col slice for its 32-row band
    {
        int cb = wc*32 + 2*(lane & 3);
        float gv[4][2], bv[4][2];
        #pragma unroll
        for (int nt = 0; nt < 4; nt++) {
            gv[nt][0] = gamma[cb + nt*8];  gv[nt][1] = gamma[cb + nt*8 + 1];
            bv[nt][0] = beta[cb + nt*8];   bv[nt][1] = beta[cb + nt*8 + 1];
        }
        #pragma unroll
        for (int mt = 0; mt < 2; mt++) {
            int rA = wr*32 + mt*16 + (lane >> 2);
            int rB = rA + 8;
            float muA = s_s1[rA] * (1.0f/128.0f);
            float vrA = s_s2[rA] * (1.0f/128.0f) - muA*muA;
            float ivA = 1.0f / sqrtf(vrA + 1e-5f);
            float muB = s_s1[rB] * (1.0f/128.0f);
            float vrB = s_s2[rB] * (1.0f/128.0f) - muB*muB;
            float ivB = 1.0f / sqrtf(vrB + 1e-5f);
            float* opA = out + ((size_t)row0*Kv + rA) * CD;
            float* opB = out + ((size_t)row0*Kv + rB) * CD;
            #pragma unroll
            for (int nt = 0; nt < 4; nt++) {
                int c = cb + nt*8;
                float2 oA, oB;
                oA.x = (acc[mt][nt][0] - muA)*ivA*gv[nt][0] + bv[nt][0];
                oA.y = (acc[mt][nt][1] - muA)*ivA*gv[nt][1] + bv[nt][1];
                oB.x = (acc[mt][nt][2] - muB)*ivB*gv[nt][0] + bv[nt][0];
                oB.y = (acc[mt][nt][3] - muB)*ivB*gv[nt][1] + bv[nt][1];
                *(float2*)(opA + c) = oA;
                *(float2*)(opB + c) = oB;
            }
        }
    }
}

// ---------------------------------------------------------------------------
// Launch
// ---------------------------------------------------------------------------
extern "C" void kernel_launch(void* const* d_in, const int* in_sizes, int n_in,
                              void* d_out, int out_size) {
    const float* X     = (const float*)d_in[0];
    const float* mask  = (const float*)d_in[1];
    const int*   ridx  = (const int*)  d_in[2];
    const int*   chl   = (const int*)  d_in[3];
    const float* Wpos  = (const float*)d_in[4];
    const float* bpos  = (const float*)d_in[5];
    const float* Wedge = (const float*)d_in[6];
    const float* gamma = (const float*)d_in[7];
    const float* beta  = (const float*)d_in[8];
    float* out = (float*)d_out;

    const int k2_smem = (Lv*3 + 4*Lv)*4 + 4*256*8;   // 65536 B
    cudaFuncSetAttribute(k2_topk, cudaFuncAttributeMaxDynamicSharedMemorySize, k2_smem);
    cudaFuncSetAttribute(k3_mma,  cudaFuncAttributeMaxDynamicSharedMemorySize, S_TOT);

    k0_prepW<<<(NKSG*16*32 + 255)/256, 256>>>(Wedge);
    k1_atoms<<<(Bv*Lv + 255)/256, 256>>>(X);
    k2_topk<<<Bv*Lv/4, 256, k2_smem>>>(mask);

    long long e_elems = (long long)Bv*Lv*Kv*CD;
    int write_idx = ((long long)out_size >= e_elems + (long long)Bv*Lv*Kv) ? 1 : 0;
    k3_mma<<<GRID3, 256, S_TOT>>>(ridx, chl, Wpos, bpos, gamma, beta, out, write_idx);
}

// round 16
// speedup vs baseline: 1.0817x; 1.0075x over previous
#include <cuda_runtime.h>
#include <cuda_fp16.h>
#include <cstdint>
#include <math.h>

#define Bv 4
#define Lv 2048
#define Kv 32
#define CD 128
#define NCH 7           // K chunks of 64
#define NKSG 28         // total k-steps of 16 (26 real)
#define GRID3 (Bv*Lv/2) // 4096 CTAs, 2 residues (64 edges) each

// Scratch (__device__ globals; no allocation allowed)
__device__ float g_atoms[Bv*Lv*5*3];
__device__ float g_ca[Bv*Lv*3];
__device__ int   g_eidx[Bv*Lv*Kv];
__device__ float g_dn[Bv*Lv*Kv];
// W in mma b-fragment layout: [ksg(28)][nt(16)][lane(32)] -> uint2 {b0,b1}, single fp16
__device__ uint2 g_Wf[NKSG*16*32];

__constant__ int c_PA[24] = {0,2,3,4,1,1,1,1,0,0,0,4,4,3,0,2,3,4,2,3,4,2,3,2};
__constant__ int c_PB[24] = {0,2,3,4,0,2,3,4,2,3,4,2,3,2,1,1,1,1,0,0,0,4,4,3};

__device__ __forceinline__ unsigned smem_u32(const void* p) {
    unsigned a;
    asm("{ .reg .u64 t; cvta.to.shared.u64 t, %1; cvt.u32.u64 %0, t; }" : "=r"(a) : "l"(p));
    return a;
}
__device__ __forceinline__ void ldsm4(unsigned* r, unsigned addr) {
    asm volatile("ldmatrix.sync.aligned.m8n8.x4.shared.b16 {%0,%1,%2,%3}, [%4];"
        : "=r"(r[0]), "=r"(r[1]), "=r"(r[2]), "=r"(r[3]) : "r"(addr));
}
__device__ __forceinline__ void mma16816(float* c, const unsigned* a, unsigned b0, unsigned b1) {
    asm volatile("mma.sync.aligned.m16n8k16.row.col.f32.f16.f16.f32 "
        "{%0,%1,%2,%3},{%4,%5,%6,%7},{%8,%9},{%0,%1,%2,%3};"
        : "+f"(c[0]), "+f"(c[1]), "+f"(c[2]), "+f"(c[3])
        : "r"(a[0]), "r"(a[1]), "r"(a[2]), "r"(a[3]), "r"(b0), "r"(b1));
}
__device__ __forceinline__ unsigned long long umin64(unsigned long long a, unsigned long long b) {
    return a < b ? a : b;
}

// ---------------------------------------------------------------------------
// k0: W_edge (416x128 f32) -> single fp16 fragments in mma b-frag layout.
// ---------------------------------------------------------------------------
__global__ void k0_prepW(const float* __restrict__ W) {
    int idx = blockIdx.x * 256 + threadIdx.x;     // NKSG*16*32 = 14336
    if (idx >= NKSG*16*32) return;
    int lane = idx & 31;
    int nt   = (idx >> 5) & 15;
    int ksg  = idx >> 9;
    int n  = nt*8 + (lane >> 2);
    int k0 = ksg*16 + (lane & 3)*2;
    unsigned r[2];
    #pragma unroll
    for (int h = 0; h < 2; h++) {
        int f0 = k0 + h*8;
        float v0 = (f0   < 416) ? W[f0 * CD + n]     : 0.0f;
        float v1 = (f0+1 < 416) ? W[(f0+1) * CD + n] : 0.0f;
        __half2 p = __floats2half2_rn(v0, v1);
        r[h] = *(unsigned*)&p;
    }
    g_Wf[idx] = make_uint2(r[0], r[1]);
}

// ---------------------------------------------------------------------------
// k1: atom table (N, Ca, C, O, Cb)
// ---------------------------------------------------------------------------
__global__ void k1_atoms(const float* __restrict__ X) {
    int i = blockIdx.x * blockDim.x + threadIdx.x;
    if (i >= Bv*Lv) return;
    const float* x = X + (size_t)i * 12;
    float Nx=x[0],Ny=x[1],Nz=x[2];
    float Ax=x[3],Ay=x[4],Az=x[5];
    float Cx=x[6],Cy=x[7],Cz=x[8];
    float Ox=x[9],Oy=x[10],Oz=x[11];
    float bx=Ax-Nx, by=Ay-Ny, bz=Az-Nz;
    float cx=Cx-Ax, cy=Cy-Ay, cz=Cz-Az;
    float ax=by*cz-bz*cy, ay=bz*cx-bx*cz, az=bx*cy-by*cx;
    float Cbx = -0.58273431f*ax + 0.56802827f*bx - 0.54067466f*cx + Ax;
    float Cby = -0.58273431f*ay + 0.56802827f*by - 0.54067466f*cy + Ay;
    float Cbz = -0.58273431f*az + 0.56802827f*bz - 0.54067466f*cz + Az;
    float* p = g_atoms + (size_t)i * 15;
    p[0]=Nx; p[1]=Ny; p[2]=Nz;
    p[3]=Ax; p[4]=Ay; p[5]=Az;
    p[6]=Cx; p[7]=Cy; p[8]=Cz;
    p[9]=Ox; p[10]=Oy; p[11]=Oz;
    p[12]=Cbx; p[13]=Cby; p[14]=Cbz;
    g_ca[i*3+0]=Ax; g_ca[i*3+1]=Ay; g_ca[i*3+2]=Az;
}

// ---------------------------------------------------------------------------
// k2: top-K, 4 rows per 256-thread CTA. No Cα smem staging: coordinates are
// read straight from g_ca (L1/L2-hot, reused x4 rows in registers). smem =
// 40KB -> 5 CTAs/SM (was 3), hiding the serial selection chain.
// ---------------------------------------------------------------------------
__global__ void __launch_bounds__(256)
k2_topk(const float* __restrict__ mask) {
    extern __shared__ char smem_raw[];
    float* d_s  = (float*)smem_raw;                                   // 4*2048 f32 (32KB)
    unsigned long long* tmin = (unsigned long long*)(d_s + 4*Lv);     // 4*256 u64 (8KB)
    __shared__ int s_maxi[4];

    int tid  = threadIdx.x;
    int wid  = tid >> 5, lane = tid & 31;
    int row0 = blockIdx.x * 4;
    int b    = row0 >> 11;

    if (tid < 4) s_maxi[tid] = 0;
    __syncthreads();

    const float* cab = g_ca + (size_t)b * Lv * 3;
    float cx[4], cy[4], cz[4], mi[4];
    #pragma unroll
    for (int r = 0; r < 4; r++) {
        int li = (row0 + r) & (Lv-1);
        cx[r] = cab[li*3+0]; cy[r] = cab[li*3+1]; cz[r] = cab[li*3+2];
        mi[r] = mask[(size_t)row0 + r];
    }
    const float* mb = mask + (size_t)b * Lv;

    int j0 = tid * 8;
    float Dreg[4][8], mbj[8];
    float lmax[4] = {0.f, 0.f, 0.f, 0.f};
    #pragma unroll
    for (int s = 0; s < 8; s++) {
        int j = j0 + s;
        float px = cab[j*3+0], py = cab[j*3+1], pz = cab[j*3+2];
        mbj[s] = mb[j];
        #pragma unroll
        for (int r = 0; r < 4; r++) {
            float dx = cx[r]-px, dy = cy[r]-py, dz = cz[r]-pz;
            float d  = sqrtf(dx*dx + dy*dy + dz*dz + 1e-6f);
            float D  = mi[r] * mbj[s] * d;
            Dreg[r][s] = D;
            lmax[r] = fmaxf(lmax[r], D);
        }
    }
    #pragma unroll
    for (int r = 0; r < 4; r++) {
        float v = lmax[r];
        #pragma unroll
        for (int o = 16; o; o >>= 1) v = fmaxf(v, __shfl_xor_sync(0xffffffffu, v, o));
        if (lane == 0) atomicMax(&s_maxi[r], __float_as_int(v));
    }
    __syncthreads();

    #pragma unroll
    for (int r = 0; r < 4; r++) {
        float Dmax = __int_as_float(s_maxi[r]);
        unsigned long long mn = ~0ULL;
        #pragma unroll
        for (int s = 0; s < 8; s++) {
            int j = j0 + s;
            float m2 = mi[r] * mbj[s];
            float Dadj = Dreg[r][s] + (1.0f - m2) * Dmax;
            d_s[r*Lv + j] = Dadj;
            unsigned long long k = (((unsigned long long)__float_as_uint(Dadj)) << 32) | (unsigned)j;
            mn = umin64(mn, k);
        }
        tmin[r*256 + tid] = mn;
    }
    __syncthreads();

    if (wid < 4) {
        int r = wid;
        int row = row0 + r;
        float* dr = d_s + r*Lv;
        unsigned long long m[8];
        #pragma unroll
        for (int s = 0; s < 8; s++) m[s] = tmin[r*256 + lane*8 + s];

        for (int rnd = 0; rnd < Kv; rnd++) {
            unsigned long long w = m[0];
            #pragma unroll
            for (int s = 1; s < 8; s++) w = umin64(w, m[s]);
            #pragma unroll
            for (int o = 16; o; o >>= 1) {
                unsigned long long v = __shfl_xor_sync(0xffffffffu, w, o);
                w = umin64(w, v);
            }
            int j = (int)(unsigned)(w & 0xffffffffu);
            if (lane == 0) {
                g_eidx[(size_t)row*Kv + rnd] = j;
                g_dn[(size_t)row*Kv + rnd]   = __uint_as_float((unsigned)(w >> 32));
            }
            int t = j >> 3;
            if ((t >> 3) == lane) {
                dr[j] = __int_as_float(0x7f800000);
                unsigned long long nm = ~0ULL;
                #pragma unroll
                for (int s = 0; s < 8; s++) {
                    int jj = t*8 + s;
                    float Dv = dr[jj];
                    unsigned long long k = (((unsigned long long)__float_as_uint(Dv)) << 32) | (unsigned)jj;
                    nm = umin64(nm, k);
                }
                m[t & 7] = nm;
            }
        }
    }
}

// ---------------------------------------------------------------------------
// k3: fused feature-build + single-pass fp16 mma GEMM + LayerNorm.
// (R15-proven: CTA = 2 residues, warp tile 32Mx32N, 3 CTAs/SM, A dbl-buffered)
// ---------------------------------------------------------------------------
#define S_A0  0                           // 64*144 = 9216
#define S_A1  9216                        // -> 18432
#define S_NBA 18432                       // 64*15 f32 = 3840 -> 22272
#define S_QA  22272                       // 30 f32 -> 128 (padded)
#define S_JV  22400                       // 64 int -> 256
#define S_DN  22656                       // 64 f32 -> 256
#define S_DP  22912                       // 64 int -> 256
#define S_S1  23168                       // 64 f32 -> 256
#define S_S2  23424                       // 64 f32 -> 256
#define S_TOT 23680

__global__ void __launch_bounds__(256, 3)
k3_mma(const int* __restrict__ ridx, const int* __restrict__ chl,
       const float* __restrict__ Wpos, const float* __restrict__ bpos,
       const float* __restrict__ gamma, const float* __restrict__ beta,
       float* __restrict__ out, int write_idx) {
    extern __shared__ unsigned char sm[];
    unsigned sb = smem_u32(sm);
    int tid  = threadIdx.x;
    int wid  = tid >> 5, lane = tid & 31;
    int wr   = wid >> 2;
    int wc   = wid & 3;
    int row0 = blockIdx.x * 2;
    int b    = row0 >> 11;

    float* nbA  = (float*)(sm + S_NBA);
    float* qa   = (float*)(sm + S_QA);
    int*   jv   = (int*)  (sm + S_JV);
    float* Dn   = (float*)(sm + S_DN);
    int*   dpos = (int*)  (sm + S_DP);
    float* s_s1 = (float*)(sm + S_S1);
    float* s_s2 = (float*)(sm + S_S2);

    if (tid < 64) {
        int r = tid >> 5;
        int brow = row0 + r;
        int j = g_eidx[(size_t)row0*Kv + tid];
        jv[tid] = j;
        Dn[tid] = g_dn[(size_t)row0*Kv + tid];
        int off = ridx[brow] - ridx[(size_t)b*Lv + j];
        int ech = (chl[brow] == chl[(size_t)b*Lv + j]) ? 1 : 0;
        int d = off + 32;
        d = d < 0 ? 0 : (d > 64 ? 64 : d);
        dpos[tid] = ech ? d : 65;
        s_s1[tid] = 0.0f;
        s_s2[tid] = 0.0f;
    }
    if (tid >= 160 && tid < 190) {
        int t = tid - 160;
        qa[t] = g_atoms[(size_t)(row0 + t/15)*15 + (t%15)];
    }
    __syncthreads();

    for (int t = tid; t < 64*15; t += 256) {
        nbA[t] = g_atoms[((size_t)b*Lv + jv[t/15])*15 + (t%15)];
    }
    __syncthreads();

    int e  = tid & 63;
    int ss = tid >> 6;
    int r  = e >> 5;

    auto build_chunk = [&](int kcb, unsigned abuf) {
        int S = kcb*4 + ss;
        if (S < 26) {
            float vals[16];
            if (S == 0) {
                const float4* wp = (const float4*)(Wpos + dpos[e]*16);
                const float4* bb = (const float4*)bpos;
                #pragma unroll
                for (int q = 0; q < 4; q++) {
                    float4 a = wp[q], c = bb[q];
                    vals[q*4+0]=a.x+c.x; vals[q*4+1]=a.y+c.y; vals[q*4+2]=a.z+c.z; vals[q*4+3]=a.w+c.w;
                }
            } else {
                float D;
                if (S == 1) D = Dn[e];
                else {
                    int p = S - 2;
                    const float* A  = qa  + r*15 + c_PA[p]*3;
                    const float* Bp = nbA + e*15 + c_PB[p]*3;
                    float dx=A[0]-Bp[0], dy=A[1]-Bp[1], dz=A[2]-Bp[2];
                    D = sqrtf(dx*dx + dy*dy + dz*dz + 1e-6f);
                }
                #pragma unroll
                for (int m = 0; m < 16; m++) {
                    float mu = 2.0f + (float)m * (4.0f/3.0f);
                    float z = (D - mu) * 0.8f;
                    vals[m] = __expf(-(z*z));
                }
            }
            unsigned byteoff = abuf + (unsigned)e*144 + (unsigned)ss*32;
            #pragma unroll
            for (int q = 0; q < 2; q++) {
                unsigned hp[4];
                #pragma unroll
                for (int j4 = 0; j4 < 4; j4++) {
                    __half2 h2 = __floats2half2_rn(vals[q*8 + j4*2], vals[q*8 + j4*2 + 1]);
                    hp[j4] = *(unsigned*)&h2;
                }
                *(uint4*)(sm + byteoff + q*16) = make_uint4(hp[0],hp[1],hp[2],hp[3]);
            }
        }
    };

    float acc[2][4][4];
    #pragma unroll
    for (int mt = 0; mt < 2; mt++)
        #pragma unroll
        for (int nt = 0; nt < 4; nt++) {
            acc[mt][nt][0]=0.f; acc[mt][nt][1]=0.f; acc[mt][nt][2]=0.f; acc[mt][nt][3]=0.f;
        }

    int arow  = lane & 15;
    int acol8 = (lane >> 4) * 8;
    const uint2* __restrict__ Wf = g_Wf;

    build_chunk(0, S_A0);
    __syncthreads();

    for (int kc = 0; kc < NCH; kc++) {
        unsigned cur = (kc & 1) ? S_A1 : S_A0;
        unsigned nxt = (kc & 1) ? S_A0 : S_A1;
        unsigned aBase = sb + cur + (unsigned)(wr*32)*144;

        int nks = (kc == NCH-1) ? 2 : 4;
        for (int ks = 0; ks < nks; ks++) {
            int ksg = kc*4 + ks;
            int k0  = ks * 16;
            uint2 bf[4];
            #pragma unroll
            for (int nt = 0; nt < 4; nt++)
                bf[nt] = Wf[((ksg*16) + (wc*4 + nt))*32 + lane];
            unsigned a[2][4];
            #pragma unroll
            for (int mt = 0; mt < 2; mt++)
                ldsm4(a[mt], aBase + (unsigned)(mt*16 + arow)*144 + (unsigned)(k0 + acol8)*2);
            #pragma unroll
            for (int mt = 0; mt < 2; mt++)
                #pragma unroll
                for (int nt = 0; nt < 4; nt++)
                    mma16816(acc[mt][nt], a[mt], bf[nt].x, bf[nt].y);
        }

        if (kc + 1 < NCH) build_chunk(kc + 1, nxt);
        __syncthreads();
    }

    if (write_idx && tid < 64) {
        out[(size_t)Bv*Lv*Kv*CD + (size_t)row0*Kv + tid] = (float)jv[tid];
    }

    #pragma unroll
    for (int mt = 0; mt < 2; mt++) {
        float pA1=0.f, pA2=0.f, pB1=0.f, pB2=0.f;
        #pragma unroll
        for (int nt = 0; nt < 4; nt++) {
            float v0 = acc[mt][nt][0], v1 = acc[mt][nt][1];
            float v2 = acc[mt][nt][2], v3 = acc[mt][nt][3];
            pA1 += v0 + v1;  pA2 += v0*v0 + v1*v1;
            pB1 += v2 + v3;  pB2 += v2*v2 + v3*v3;
        }
        #pragma unroll
        for (int o = 1; o <= 2; o <<= 1) {
            pA1 += __shfl_xor_sync(0xffffffffu, pA1, o);
            pA2 += __shfl_xor_sync(0xffffffffu, pA2, o);
            pB1 += __shfl_xor_sync(0xffffffffu, pB1, o);
            pB2 += __shfl_xor_sync(0xffffffffu, pB2, o);
        }
        if ((lane & 3) == 0) {
            int rA = wr*32 + mt*16 + (lane >> 2);
            atomicAdd(&s_s1[rA],     pA1);
            atomicAdd(&s_s2[rA],     pA2);
            atomicAdd(&s_s1[rA + 8], pB1);
            atomicAdd(&s_s2[rA + 8], pB2);
        }
    }
    __syncthreads();

    {
        int cb = wc*32 + 2*(lane & 3);
        float gv[4][2], bv[4][2];
        #pragma unroll
        for (int nt = 0; nt < 4; nt++) {
            gv[nt][0] = gamma[cb + nt*8];  gv[nt][1] = gamma[cb + nt*8 + 1];
            bv[nt][0] = beta[cb + nt*8];   bv[nt][1] = beta[cb + nt*8 + 1];
        }
        #pragma unroll
        for (int mt = 0; mt < 2; mt++) {
            int rA = wr*32 + mt*16 + (lane >> 2);
            int rB = rA + 8;
            float muA = s_s1[rA] * (1.0f/128.0f);
            float vrA = s_s2[rA] * (1.0f/128.0f) - muA*muA;
            float ivA = 1.0f / sqrtf(vrA + 1e-5f);
            float muB = s_s1[rB] * (1.0f/128.0f);
            float vrB = s_s2[rB] * (1.0f/128.0f) - muB*muB;
            float ivB = 1.0f / sqrtf(vrB + 1e-5f);
            float* opA = out + ((size_t)row0*Kv + rA) * CD;
            float* opB = out + ((size_t)row0*Kv + rB) * CD;
            #pragma unroll
            for (int nt = 0; nt < 4; nt++) {
                int c = cb + nt*8;
                float2 oA, oB;
                oA.x = (acc[mt][nt][0] - muA)*ivA*gv[nt][0] + bv[nt][0];
                oA.y = (acc[mt][nt][1] - muA)*ivA*gv[nt][1] + bv[nt][1];
                oB.x = (acc[mt][nt][2] - muB)*ivB*gv[nt][0] + bv[nt][0];
                oB.y = (acc[mt][nt][3] - muB)*ivB*gv[nt][1] + bv[nt][1];
                *(float2*)(opA + c) = oA;
                *(float2*)(opB + c) = oB;
            }
        }
    }
}

// ---------------------------------------------------------------------------
// Launch
// ---------------------------------------------------------------------------
extern "C" void kernel_launch(void* const* d_in, const int* in_sizes, int n_in,
                              void* d_out, int out_size) {
    const float* X     = (const float*)d_in[0];
    const float* mask  = (const float*)d_in[1];
    const int*   ridx  = (const int*)  d_in[2];
    const int*   chl   = (const int*)  d_in[3];
    const float* Wpos  = (const float*)d_in[4];
    const float* bpos  = (const float*)d_in[5];
    const float* Wedge = (const float*)d_in[6];
    const float* gamma = (const float*)d_in[7];
    const float* beta  = (const float*)d_in[8];
    float* out = (float*)d_out;

    const int k2_smem = 4*Lv*4 + 4*256*8;            // 32768 + 8192 = 40960 B
    cudaFuncSetAttribute(k2_topk, cudaFuncAttributeMaxDynamicSharedMemorySize, k2_smem);
    cudaFuncSetAttribute(k3_mma,  cudaFuncAttributeMaxDynamicSharedMemorySize, S_TOT);

    k0_prepW<<<(NKSG*16*32 + 255)/256, 256>>>(Wedge);
    k1_atoms<<<(Bv*Lv + 255)/256, 256>>>(X);
    k2_topk<<<Bv*Lv/4, 256, k2_smem>>>(mask);

    long long e_elems = (long long)Bv*Lv*Kv*CD;
    int write_idx = ((long long)out_size >= e_elems + (long long)Bv*Lv*Kv) ? 1 : 0;
    k3_mma<<<GRID3, 256, S_TOT>>>(ridx, chl, Wpos, bpos, gamma, beta, out, write_idx);
}

// round 17
// speedup vs baseline: 1.1009x; 1.0177x over previous
#include <cuda_runtime.h>
#include <cuda_fp16.h>
#include <cstdint>
#include <math.h>

#define Bv 4
#define Lv 2048
#define Kv 32
#define CD 128
#define NCH 7           // K chunks of 64
#define NKSG 28         // total k-steps of 16 (26 real)
#define GRID3 (Bv*Lv/2) // 4096 CTAs, 2 residues (64 edges) each

// Scratch (__device__ globals; no allocation allowed)
__device__ float g_atoms[Bv*Lv*5*3];
__device__ float g_ca[Bv*Lv*3];
__device__ int   g_eidx[Bv*Lv*Kv];
__device__ float g_dn[Bv*Lv*Kv];
__device__ uint2 g_Wf[NKSG*16*32];   // W fragments [ksg][nt][lane]

__constant__ int c_PA[24] = {0,2,3,4,1,1,1,1,0,0,0,4,4,3,0,2,3,4,2,3,4,2,3,2};
__constant__ int c_PB[24] = {0,2,3,4,0,2,3,4,2,3,4,2,3,2,1,1,1,1,0,0,0,4,4,3};

__device__ __forceinline__ unsigned smem_u32(const void* p) {
    unsigned a;
    asm("{ .reg .u64 t; cvta.to.shared.u64 t, %1; cvt.u32.u64 %0, t; }" : "=r"(a) : "l"(p));
    return a;
}
__device__ __forceinline__ void ldsm4(unsigned* r, unsigned addr) {
    asm volatile("ldmatrix.sync.aligned.m8n8.x4.shared.b16 {%0,%1,%2,%3}, [%4];"
        : "=r"(r[0]), "=r"(r[1]), "=r"(r[2]), "=r"(r[3]) : "r"(addr));
}
__device__ __forceinline__ void mma16816(float* c, const unsigned* a, unsigned b0, unsigned b1) {
    asm volatile("mma.sync.aligned.m16n8k16.row.col.f32.f16.f16.f32 "
        "{%0,%1,%2,%3},{%4,%5,%6,%7},{%8,%9},{%0,%1,%2,%3};"
        : "+f"(c[0]), "+f"(c[1]), "+f"(c[2]), "+f"(c[3])
        : "r"(a[0]), "r"(a[1]), "r"(a[2]), "r"(a[3]), "r"(b0), "r"(b1));
}
__device__ __forceinline__ unsigned long long umin64(unsigned long long a, unsigned long long b) {
    return a < b ? a : b;
}

// ---------------------------------------------------------------------------
// k01: merged prep. Blocks [0,56): W_edge -> fp16 b-fragments.
//      Blocks [56,88): atom table (N, Ca, C, O, Cb).
// ---------------------------------------------------------------------------
__global__ void k01_prep(const float* __restrict__ X, const float* __restrict__ W) {
    if (blockIdx.x < 56) {
        int idx = blockIdx.x * 256 + threadIdx.x;     // NKSG*16*32 = 14336
        if (idx >= NKSG*16*32) return;
        int lane = idx & 31;
        int nt   = (idx >> 5) & 15;
        int ksg  = idx >> 9;
        int n  = nt*8 + (lane >> 2);
        int k0 = ksg*16 + (lane & 3)*2;
        unsigned r[2];
        #pragma unroll
        for (int h = 0; h < 2; h++) {
            int f0 = k0 + h*8;
            float v0 = (f0   < 416) ? W[f0 * CD + n]     : 0.0f;
            float v1 = (f0+1 < 416) ? W[(f0+1) * CD + n] : 0.0f;
            __half2 p = __floats2half2_rn(v0, v1);
            r[h] = *(unsigned*)&p;
        }
        g_Wf[idx] = make_uint2(r[0], r[1]);
    } else {
        int i = (blockIdx.x - 56) * 256 + threadIdx.x;
        if (i >= Bv*Lv) return;
        const float* x = X + (size_t)i * 12;
        float Nx=x[0],Ny=x[1],Nz=x[2];
        float Ax=x[3],Ay=x[4],Az=x[5];
        float Cx=x[6],Cy=x[7],Cz=x[8];
        float Ox=x[9],Oy=x[10],Oz=x[11];
        float bx=Ax-Nx, by=Ay-Ny, bz=Az-Nz;
        float cx=Cx-Ax, cy=Cy-Ay, cz=Cz-Az;
        float ax=by*cz-bz*cy, ay=bz*cx-bx*cz, az=bx*cy-by*cx;
        float Cbx = -0.58273431f*ax + 0.56802827f*bx - 0.54067466f*cx + Ax;
        float Cby = -0.58273431f*ay + 0.56802827f*by - 0.54067466f*cy + Ay;
        float Cbz = -0.58273431f*az + 0.56802827f*bz - 0.54067466f*cz + Az;
        float* p = g_atoms + (size_t)i * 15;
        p[0]=Nx; p[1]=Ny; p[2]=Nz;
        p[3]=Ax; p[4]=Ay; p[5]=Az;
        p[6]=Cx; p[7]=Cy; p[8]=Cz;
        p[9]=Ox; p[10]=Oy; p[11]=Oz;
        p[12]=Cbx; p[13]=Cby; p[14]=Cbz;
        g_ca[i*3+0]=Ax; g_ca[i*3+1]=Ay; g_ca[i*3+2]=Az;
    }
}

// ---------------------------------------------------------------------------
// k2: top-K, 4 rows per 256-thread CTA. STRIDED column ownership: thread t
// owns columns {t + 256*s} -> lane-consecutive smem stores (conflict-free)
// and coalesced global loads. Selection (warp per row) uses identical keys
// -> exact jax.lax.top_k semantics preserved. Owner of column j = j & 255.
// ---------------------------------------------------------------------------
__global__ void __launch_bounds__(256)
k2_topk(const float* __restrict__ mask) {
    extern __shared__ char smem_raw[];
    float* d_s  = (float*)smem_raw;                                   // 4*2048 f32 (32KB)
    unsigned long long* tmin = (unsigned long long*)(d_s + 4*Lv);     // 4*256 u64 (8KB)
    __shared__ int s_maxi[4];

    int tid  = threadIdx.x;
    int wid  = tid >> 5, lane = tid & 31;
    int row0 = blockIdx.x * 4;
    int b    = row0 >> 11;

    if (tid < 4) s_maxi[tid] = 0;
    __syncthreads();

    const float* cab = g_ca + (size_t)b * Lv * 3;
    float cx[4], cy[4], cz[4], mi[4];
    #pragma unroll
    for (int r = 0; r < 4; r++) {
        int li = (row0 + r) & (Lv-1);
        cx[r] = cab[li*3+0]; cy[r] = cab[li*3+1]; cz[r] = cab[li*3+2];
        mi[r] = mask[(size_t)row0 + r];
    }
    const float* mb = mask + (size_t)b * Lv;

    float Dreg[4][8], mbj[8];
    float lmax[4] = {0.f, 0.f, 0.f, 0.f};
    #pragma unroll
    for (int s = 0; s < 8; s++) {
        int j = tid + (s << 8);                 // strided ownership
        float px = cab[j*3+0], py = cab[j*3+1], pz = cab[j*3+2];
        mbj[s] = mb[j];
        #pragma unroll
        for (int r = 0; r < 4; r++) {
            float dx = cx[r]-px, dy = cy[r]-py, dz = cz[r]-pz;
            float d  = sqrtf(dx*dx + dy*dy + dz*dz + 1e-6f);
            float D  = mi[r] * mbj[s] * d;
            Dreg[r][s] = D;
            lmax[r] = fmaxf(lmax[r], D);
        }
    }
    #pragma unroll
    for (int r = 0; r < 4; r++) {
        float v = lmax[r];
        #pragma unroll
        for (int o = 16; o; o >>= 1) v = fmaxf(v, __shfl_xor_sync(0xffffffffu, v, o));
        if (lane == 0) atomicMax(&s_maxi[r], __float_as_int(v));
    }
    __syncthreads();

    #pragma unroll
    for (int r = 0; r < 4; r++) {
        float Dmax = __int_as_float(s_maxi[r]);
        unsigned long long mn = ~0ULL;
        #pragma unroll
        for (int s = 0; s < 8; s++) {
            int j = tid + (s << 8);
            float m2 = mi[r] * mbj[s];
            float Dadj = Dreg[r][s] + (1.0f - m2) * Dmax;
            d_s[r*Lv + j] = Dadj;                // conflict-free store
            unsigned long long k = (((unsigned long long)__float_as_uint(Dadj)) << 32) | (unsigned)j;
            mn = umin64(mn, k);
        }
        tmin[r*256 + tid] = mn;
    }
    __syncthreads();

    if (wid < 4) {
        int r = wid;
        int row = row0 + r;
        float* dr = d_s + r*Lv;
        unsigned long long m[8];
        #pragma unroll
        for (int s = 0; s < 8; s++) m[s] = tmin[r*256 + lane*8 + s];

        for (int rnd = 0; rnd < Kv; rnd++) {
            unsigned long long w = m[0];
            #pragma unroll
            for (int s = 1; s < 8; s++) w = umin64(w, m[s]);
            #pragma unroll
            for (int o = 16; o; o >>= 1) {
                unsigned long long v = __shfl_xor_sync(0xffffffffu, w, o);
                w = umin64(w, v);
            }
            int j = (int)(unsigned)(w & 0xffffffffu);
            if (lane == 0) {
                g_eidx[(size_t)row*Kv + rnd] = j;
                g_dn[(size_t)row*Kv + rnd]   = __uint_as_float((unsigned)(w >> 32));
            }
            int t = j & 255;                     // owner thread (strided map)
            if ((t >> 3) == lane) {
                dr[j] = __int_as_float(0x7f800000);
                unsigned long long nm = ~0ULL;
                #pragma unroll
                for (int s = 0; s < 8; s++) {
                    int jj = t + (s << 8);
                    float Dv = dr[jj];
                    unsigned long long k = (((unsigned long long)__float_as_uint(Dv)) << 32) | (unsigned)jj;
                    nm = umin64(nm, k);
                }
                m[t & 7] = nm;
            }
        }
    }
}

// ---------------------------------------------------------------------------
// k3: fused feature-build + single-pass fp16 mma GEMM + LayerNorm.
// (R15/R16-proven: CTA = 2 residues, warp tile 32Mx32N, A dbl-buffered)
// ---------------------------------------------------------------------------
#define S_A0  0                           // 64*144 = 9216
#define S_A1  9216                        // -> 18432
#define S_NBA 18432                       // 64*15 f32 = 3840 -> 22272
#define S_QA  22272                       // 30 f32 -> 128 (padded)
#define S_JV  22400                       // 64 int -> 256
#define S_DN  22656                       // 64 f32 -> 256
#define S_DP  22912                       // 64 int -> 256
#define S_S1  23168                       // 64 f32 -> 256
#define S_S2  23424                       // 64 f32 -> 256
#define S_TOT 23680

__global__ void __launch_bounds__(256, 3)
k3_mma(const int* __restrict__ ridx, const int* __restrict__ chl,
       const float* __restrict__ Wpos, const float* __restrict__ bpos,
       const float* __restrict__ gamma, const float* __restrict__ beta,
       float* __restrict__ out, int write_idx) {
    extern __shared__ unsigned char sm[];
    unsigned sb = smem_u32(sm);
    int tid  = threadIdx.x;
    int wid  = tid >> 5, lane = tid & 31;
    int wr   = wid >> 2;
    int wc   = wid & 3;
    int row0 = blockIdx.x * 2;
    int b    = row0 >> 11;

    float* nbA  = (float*)(sm + S_NBA);
    float* qa   = (float*)(sm + S_QA);
    int*   jv   = (int*)  (sm + S_JV);
    float* Dn   = (float*)(sm + S_DN);
    int*   dpos = (int*)  (sm + S_DP);
    float* s_s1 = (float*)(sm + S_S1);
    float* s_s2 = (float*)(sm + S_S2);

    if (tid < 64) {
        int r = tid >> 5;
        int brow = row0 + r;
        int j = g_eidx[(size_t)row0*Kv + tid];
        jv[tid] = j;
        Dn[tid] = g_dn[(size_t)row0*Kv + tid];
        int off = ridx[brow] - ridx[(size_t)b*Lv + j];
        int ech = (chl[brow] == chl[(size_t)b*Lv + j]) ? 1 : 0;
        int d = off + 32;
        d = d < 0 ? 0 : (d > 64 ? 64 : d);
        dpos[tid] = ech ? d : 65;
        s_s1[tid] = 0.0f;
        s_s2[tid] = 0.0f;
    }
    if (tid >= 160 && tid < 190) {
        int t = tid - 160;
        qa[t] = g_atoms[(size_t)(row0 + t/15)*15 + (t%15)];
    }
    __syncthreads();

    for (int t = tid; t < 64*15; t += 256) {
        nbA[t] = g_atoms[((size_t)b*Lv + jv[t/15])*15 + (t%15)];
    }
    __syncthreads();

    int e  = tid & 63;
    int ss = tid >> 6;
    int r  = e >> 5;

    auto build_chunk = [&](int kcb, unsigned abuf) {
        int S = kcb*4 + ss;
        if (S < 26) {
            float vals[16];
            if (S == 0) {
                const float4* wp = (const float4*)(Wpos + dpos[e]*16);
                const float4* bb = (const float4*)bpos;
                #pragma unroll
                for (int q = 0; q < 4; q++) {
                    float4 a = wp[q], c = bb[q];
                    vals[q*4+0]=a.x+c.x; vals[q*4+1]=a.y+c.y; vals[q*4+2]=a.z+c.z; vals[q*4+3]=a.w+c.w;
                }
            } else {
                float D;
                if (S == 1) D = Dn[e];
                else {
                    int p = S - 2;
                    const float* A  = qa  + r*15 + c_PA[p]*3;
                    const float* Bp = nbA + e*15 + c_PB[p]*3;
                    float dx=A[0]-Bp[0], dy=A[1]-Bp[1], dz=A[2]-Bp[2];
                    D = sqrtf(dx*dx + dy*dy + dz*dz + 1e-6f);
                }
                #pragma unroll
                for (int m = 0; m < 16; m++) {
                    float mu = 2.0f + (float)m * (4.0f/3.0f);
                    float z = (D - mu) * 0.8f;
                    vals[m] = __expf(-(z*z));
                }
            }
            unsigned byteoff = abuf + (unsigned)e*144 + (unsigned)ss*32;
            #pragma unroll
            for (int q = 0; q < 2; q++) {
                unsigned hp[4];
                #pragma unroll
                for (int j4 = 0; j4 < 4; j4++) {
                    __half2 h2 = __floats2half2_rn(vals[q*8 + j4*2], vals[q*8 + j4*2 + 1]);
                    hp[j4] = *(unsigned*)&h2;
                }
                *(uint4*)(sm + byteoff + q*16) = make_uint4(hp[0],hp[1],hp[2],hp[3]);
            }
        }
    };

    float acc[2][4][4];
    #pragma unroll
    for (int mt = 0; mt < 2; mt++)
        #pragma unroll
        for (int nt = 0; nt < 4; nt++) {
            acc[mt][nt][0]=0.f; acc[mt][nt][1]=0.f; acc[mt][nt][2]=0.f; acc[mt][nt][3]=0.f;
        }

    int arow  = lane & 15;
    int acol8 = (lane >> 4) * 8;
    const uint2* __restrict__ Wf = g_Wf;

    build_chunk(0, S_A0);
    __syncthreads();

    for (int kc = 0; kc < NCH; kc++) {
        unsigned cur = (kc & 1) ? S_A1 : S_A0;
        unsigned nxt = (kc & 1) ? S_A0 : S_A1;
        unsigned aBase = sb + cur + (unsigned)(wr*32)*144;

        int nks = (kc == NCH-1) ? 2 : 4;
        for (int ks = 0; ks < nks; ks++) {
            int ksg = kc*4 + ks;
            int k0  = ks * 16;
            uint2 bf[4];
            #pragma unroll
            for (int nt = 0; nt < 4; nt++)
                bf[nt] = Wf[((ksg*16) + (wc*4 + nt))*32 + lane];
            unsigned a[2][4];
            #pragma unroll
            for (int mt = 0; mt < 2; mt++)
                ldsm4(a[mt], aBase + (unsigned)(mt*16 + arow)*144 + (unsigned)(k0 + acol8)*2);
            #pragma unroll
            for (int mt = 0; mt < 2; mt++)
                #pragma unroll
                for (int nt = 0; nt < 4; nt++)
                    mma16816(acc[mt][nt], a[mt], bf[nt].x, bf[nt].y);
        }

        if (kc + 1 < NCH) build_chunk(kc + 1, nxt);
        __syncthreads();
    }

    if (write_idx && tid < 64) {
        out[(size_t)Bv*Lv*Kv*CD + (size_t)row0*Kv + tid] = (float)jv[tid];
    }

    #pragma unroll
    for (int mt = 0; mt < 2; mt++) {
        float pA1=0.f, pA2=0.f, pB1=0.f, pB2=0.f;
        #pragma unroll
        for (int nt = 0; nt < 4; nt++) {
            float v0 = acc[mt][nt][0], v1 = acc[mt][nt][1];
            float v2 = acc[mt][nt][2], v3 = acc[mt][nt][3];
            pA1 += v0 + v1;  pA2 += v0*v0 + v1*v1;
            pB1 += v2 + v3;  pB2 += v2*v2 + v3*v3;
        }
        #pragma unroll
        for (int o = 1; o <= 2; o <<= 1) {
            pA1 += __shfl_xor_sync(0xffffffffu, pA1, o);
            pA2 += __shfl_xor_sync(0xffffffffu, pA2, o);
            pB1 += __shfl_xor_sync(0xffffffffu, pB1, o);
            pB2 += __shfl_xor_sync(0xffffffffu, pB2, o);
        }
        if ((lane & 3) == 0) {
            int rA = wr*32 + mt*16 + (lane >> 2);
            atomicAdd(&s_s1[rA],     pA1);
            atomicAdd(&s_s2[rA],     pA2);
            atomicAdd(&s_s1[rA + 8], pB1);
            atomicAdd(&s_s2[rA + 8], pB2);
        }
    }
    __syncthreads();

    {
        int cb = wc*32 + 2*(lane & 3);
        float gv[4][2], bv[4][2];
        #pragma unroll
        for (int nt = 0; nt < 4; nt++) {
            gv[nt][0] = gamma[cb + nt*8];  gv[nt][1] = gamma[cb + nt*8 + 1];
            bv[nt][0] = beta[cb + nt*8];   bv[nt][1] = beta[cb + nt*8 + 1];
        }
        #pragma unroll
        for (int mt = 0; mt < 2; mt++) {
            int rA = wr*32 + mt*16 + (lane >> 2);
            int rB = rA + 8;
            float muA = s_s1[rA] * (1.0f/128.0f);
            float vrA = s_s2[rA] * (1.0f/128.0f) - muA*muA;
            float ivA = 1.0f / sqrtf(vrA + 1e-5f);
            float muB = s_s1[rB] * (1.0f/128.0f);
            float vrB = s_s2[rB] * (1.0f/128.0f) - muB*muB;
            float ivB = 1.0f / sqrtf(vrB + 1e-5f);
            float* opA = out + ((size_t)row0*Kv + rA) * CD;
            float* opB = out + ((size_t)row0*Kv + rB) * CD;
            #pragma unroll
            for (int nt = 0; nt < 4; nt++) {
                int c = cb + nt*8;
                float2 oA, oB;
                oA.x = (acc[mt][nt][0] - muA)*ivA*gv[nt][0] + bv[nt][0];
                oA.y = (acc[mt][nt][1] - muA)*ivA*gv[nt][1] + bv[nt][1];
                oB.x = (acc[mt][nt][2] - muB)*ivB*gv[nt][0] + bv[nt][0];
                oB.y = (acc[mt][nt][3] - muB)*ivB*gv[nt][1] + bv[nt][1];
                *(float2*)(opA + c) = oA;
                *(float2*)(opB + c) = oB;
            }
        }
    }
}

// ---------------------------------------------------------------------------
// Launch
// ---------------------------------------------------------------------------
extern "C" void kernel_launch(void* const* d_in, const int* in_sizes, int n_in,
                              void* d_out, int out_size) {
    const float* X     = (const float*)d_in[0];
    const float* mask  = (const float*)d_in[1];
    const int*   ridx  = (const int*)  d_in[2];
    const int*   chl   = (const int*)  d_in[3];
    const float* Wpos  = (const float*)d_in[4];
    const float* bpos  = (const float*)d_in[5];
    const float* Wedge = (const float*)d_in[6];
    const float* gamma = (const float*)d_in[7];
    const float* beta  = (const float*)d_in[8];
    float* out = (float*)d_out;

    const int k2_smem = 4*Lv*4 + 4*256*8;            // 40960 B
    cudaFuncSetAttribute(k2_topk, cudaFuncAttributeMaxDynamicSharedMemorySize, k2_smem);
    cudaFuncSetAttribute(k3_mma,  cudaFuncAttributeMaxDynamicSharedMemorySize, S_TOT);

    k01_prep<<<88, 256>>>(X, Wedge);
    k2_topk<<<Bv*Lv/4, 256, k2_smem>>>(mask);

    long long e_elems = (long long)Bv*Lv*Kv*CD;
    int write_idx = ((long long)out_size >= e_elems + (long long)Bv*Lv*Kv) ? 1 : 0;
    k3_mma<<<GRID3, 256, S_TOT>>>(ridx, chl, Wpos, bpos, gamma, beta, out, write_idx);
}